// round 15
// baseline (speedup 1.0000x reference)
#include <cuda_runtime.h>
#include <cuda_fp16.h>
#include <cstdint>

#define M_TOK 16384   // B*S
#define E_DIM 1024
#define NQ    64

// ---------------- scratch (__device__ globals; no allocs) ----------------
__device__ __half g_attn[(size_t)M_TOK * E_DIM];   // fp16 attn
__device__ __half g_x1h[(size_t)M_TOK * E_DIM];    // fp16 x1
__device__ __half g_zh[(size_t)M_TOK * E_DIM];     // A of GEMM1
__device__ __half g_wh[(size_t)E_DIM * E_DIM];     // B of GEMM1
__device__ __half g_w2h[(size_t)E_DIM * NQ];       // B of GEMM2
__device__ __half g_qh[(size_t)M_TOK * NQ];        // A of GEMM2

// ---------------- PTX helpers (compute_100-safe) -------------------------
__device__ __forceinline__ uint32_t smem_u32(const void* p) {
    uint32_t a;
    asm("{ .reg .u64 t; cvta.to.shared.u64 t, %1; cvt.u32.u64 %0, t; }" : "=r"(a) : "l"(p));
    return a;
}
__device__ __forceinline__ void cp16(uint32_t dst, const void* src) {
    asm volatile("cp.async.cg.shared.global [%0], [%1], 16;" :: "r"(dst), "l"(src));
}
#define CP_COMMIT() asm volatile("cp.async.commit_group;" ::: "memory")
#define CP_WAIT1()  asm volatile("cp.async.wait_group 1;" ::: "memory")
#define CP_WAIT2()  asm volatile("cp.async.wait_group 2;" ::: "memory")
#define CP_WAIT0()  asm volatile("cp.async.wait_group 0;" ::: "memory")

#define LDSM4(r, addr)                                                        \
    asm volatile("ldmatrix.sync.aligned.m8n8.x4.shared.b16 {%0,%1,%2,%3}, [%4];" \
        : "=r"((r)[0]), "=r"((r)[1]), "=r"((r)[2]), "=r"((r)[3]) : "r"(addr))

#define MMA16816(d, a, b0, b1)                                                \
    asm volatile("mma.sync.aligned.m16n8k16.row.col.f32.f16.f16.f32 "         \
        "{%0,%1,%2,%3}, {%4,%5,%6,%7}, {%8,%9}, {%0,%1,%2,%3};"               \
        : "+f"((d)[0]), "+f"((d)[1]), "+f"((d)[2]), "+f"((d)[3])              \
        : "r"((a)[0]), "r"((a)[1]), "r"((a)[2]), "r"((a)[3]),                 \
          "r"(b0), "r"(b1))

// ================= GEMM1: r10-proven fp16 GEMM (fp16 out) ================
#define BM 128
#define BN 128
#define BK 64
#define ROWB 144
#define MAT_B (128 * ROWB)           // 18432
#define STG   (2 * MAT_B)            // 36864
#define SM_BIAS (2 * STG)
#define SM_TOT  (SM_BIAS + BN * 4)

__global__ __launch_bounds__(128, 2) void mma_gemm(
    const __half* __restrict__ Ah, const __half* __restrict__ Bh,
    const float* __restrict__ bias, __half* __restrict__ Cout, int K) {
    extern __shared__ char smem[];
    const uint32_t sbase = smem_u32(smem);
    float* sbias = (float*)(smem + SM_BIAS);
    const int tid = threadIdx.x, wid = tid >> 5, lane = tid & 31;
    const int m0 = blockIdx.y * BM, n0 = blockIdx.x * BN;
    const int m_off = (wid & 1) * 64;
    const int n_off = (wid >> 1) * 64;

    sbias[tid] = bias[n0 + tid];

    const uint32_t aRow = (uint32_t)(m_off + (lane & 15)) * ROWB + (lane >> 4) * 16;
    const uint32_t bRow = (uint32_t)(n_off + ((lane >> 4) << 3) + (lane & 7)) * ROWB
                        + ((lane >> 3) & 1) * 16;

    float acc[4][8][4] = {};

    auto load_stage = [&](int s, int kc0) {
        uint32_t sb = sbase + s * STG;
        #pragma unroll
        for (int i = 0; i < 8; ++i) {
            int c = tid + i * 128;
            int r = c >> 3, ch = c & 7;
            uint32_t d = (uint32_t)r * ROWB + ch * 16;
            cp16(sb + d,         Ah + (size_t)(m0 + r) * K + kc0 + ch * 8);
            cp16(sb + MAT_B + d, Bh + (size_t)(n0 + r) * K + kc0 + ch * 8);
        }
        CP_COMMIT();
    };

    const int C = K / BK;
    load_stage(0, 0);

    for (int ki = 0; ki < C; ++ki) {
        int cur = ki & 1;
        if (ki + 1 < C) { load_stage(cur ^ 1, (ki + 1) * BK); CP_WAIT1(); }
        else           { CP_WAIT0(); }
        __syncthreads();

        uint32_t base = sbase + cur * STG;
        uint32_t aH = base + aRow;
        uint32_t bH = base + MAT_B + bRow;

        #pragma unroll
        for (int ks = 0; ks < 4; ++ks) {
            uint32_t ah[4][4], bh[8][2];
            #pragma unroll
            for (int mi = 0; mi < 4; ++mi)
                LDSM4(ah[mi], aH + ks * 32 + mi * 16 * ROWB);
            #pragma unroll
            for (int p = 0; p < 4; ++p) {
                uint32_t t[4];
                LDSM4(t, bH + ks * 32 + p * 16 * ROWB);
                bh[2 * p][0] = t[0]; bh[2 * p][1] = t[1];
                bh[2 * p + 1][0] = t[2]; bh[2 * p + 1][1] = t[3];
            }
            #pragma unroll
            for (int mi = 0; mi < 4; ++mi)
                #pragma unroll
                for (int ni = 0; ni < 8; ++ni)
                    MMA16816(acc[mi][ni], ah[mi], bh[ni][0], bh[ni][1]);
        }
        __syncthreads();
    }

    #pragma unroll
    for (int mi = 0; mi < 4; ++mi) {
        int m = m0 + m_off + mi * 16 + (lane >> 2);
        #pragma unroll
        for (int ni = 0; ni < 8; ++ni) {
            int nl = n_off + ni * 8 + 2 * (lane & 3);
            float2 bv = *(float2*)&sbias[nl];
            __half* p0 = Cout + (size_t)m * E_DIM + n0 + nl;
            __half* p1 = p0 + 8 * E_DIM;
            *(__half2*)p0 = __floats2half2_rn(acc[mi][ni][0] + bv.x, acc[mi][ni][1] + bv.y);
            *(__half2*)p1 = __floats2half2_rn(acc[mi][ni][2] + bv.x, acc[mi][ni][3] + bv.y);
        }
    }
}

// ================= fused GEMM2 + LN2 (v3: 4-stage W2 ring) ===============
// CTA: 16 rows x N=1024, 256 threads / 8 warps; warp covers n-slice
// [wid*16,+16) of each 128-wide W2 chunk. 4-stage ring, 1 sync/iter.
#define F_CHK  18432                 // 128*144
#define F_QS   (4 * F_CHK)           // 73728; q 16*144 = 2304
#define F_X1S  (F_QS + 2304)         // 76032; x1 16*2064 = 33024
#define F_X1RB 2064
#define F_SRED (F_X1S + 33024)       // 109056; 8*16*2 floats = 1024
#define F_MURE (F_SRED + 1024)       // 110080; 16*2 floats = 128
#define F_TOT  (F_MURE + 128)        // 110208 -> 2 CTAs/SM

__global__ __launch_bounds__(256, 2) void gemm2_ln2(
    const __half* __restrict__ qh, const __half* __restrict__ w2h,
    const float* __restrict__ flb, const __half* __restrict__ x1,
    const float* __restrict__ n2w, const float* __restrict__ n2b,
    float* __restrict__ out) {
    extern __shared__ char smem[];
    const uint32_t sbase = smem_u32(smem);
    const int tid = threadIdx.x, wid = tid >> 5, lane = tid & 31;
    const int m0 = blockIdx.x * 16;
    const int r0 = lane >> 2;

    auto load_chunk = [&](int ci) {    // W2 chunk ci -> stage ci&3 (no commit)
        uint32_t sb = sbase + (ci & 3) * F_CHK;
        #pragma unroll
        for (int i = 0; i < 4; ++i) {
            int u = tid + i * 256;
            int r = u >> 3, c = u & 7;
            cp16(sb + (uint32_t)r * 144 + c * 16,
                 w2h + (size_t)(ci * 128 + r) * NQ + c * 8);
        }
    };

    // group0: chunk0 + q + x1 ; group1: chunk1 ; group2: chunk2
    load_chunk(0);
    if (tid < 128) {
        int r = tid >> 3, c = tid & 7;
        cp16(sbase + F_QS + (uint32_t)r * 144 + c * 16,
             qh + (size_t)(m0 + r) * NQ + c * 8);
    }
    #pragma unroll
    for (int i = 0; i < 8; ++i) {
        int u = tid + i * 256;
        int r = u >> 7, c = u & 127;
        cp16(sbase + F_X1S + (uint32_t)r * F_X1RB + c * 16,
             x1 + (size_t)(m0 + r) * E_DIM + c * 8);
    }
    CP_COMMIT();
    load_chunk(1); CP_COMMIT();
    load_chunk(2); CP_COMMIT();

    float acc[8][2][4] = {};   // [chunk][n8-group][4]
    uint32_t aF[4][4];

    const uint32_t bRow = (uint32_t)((wid * 16) + ((lane >> 4) << 3) + (lane & 7)) * 144
                        + ((lane >> 3) & 1) * 16;

    for (int ci = 0; ci < 8; ++ci) {
        CP_WAIT2();               // group for chunk ci complete (2 ahead pend)
        __syncthreads();          // publish; stage (ci+3)&3 reads finished @ci-1
        if (ci + 3 < 8) load_chunk(ci + 3);
        CP_COMMIT();

        if (ci == 0) {            // A fragments once (q in group0, now visible)
            #pragma unroll
            for (int ks = 0; ks < 4; ++ks)
                LDSM4(aF[ks], sbase + F_QS + (uint32_t)(lane & 15) * 144
                                   + (lane >> 4) * 16 + ks * 32);
        }

        uint32_t Bb = sbase + (ci & 3) * F_CHK + bRow;
        #pragma unroll
        for (int ks = 0; ks < 4; ++ks) {
            uint32_t t[4];
            LDSM4(t, Bb + ks * 32);
            MMA16816(acc[ci][0], aF[ks], t[0], t[1]);
            MMA16816(acc[ci][1], aF[ks], t[2], t[3]);
        }
    }
    CP_WAIT0();

    // ---- LN2 stats (rows r0 and r0+8), u = x1 + acc + flb ----
    float s0 = 0.f, ss0 = 0.f, s1 = 0.f, ss1 = 0.f;
    #pragma unroll
    for (int ci = 0; ci < 8; ++ci)
        #pragma unroll
        for (int g = 0; g < 2; ++g) {
            int col = ci * 128 + wid * 16 + g * 8 + 2 * (lane & 3);
            float2 fb = *(const float2*)&flb[col];
            float2 xa = __half22float2(*(const __half2*)(smem + F_X1S + r0 * F_X1RB + col * 2));
            float2 xb = __half22float2(*(const __half2*)(smem + F_X1S + (r0 + 8) * F_X1RB + col * 2));
            float u00 = acc[ci][g][0] + fb.x + xa.x;
            float u01 = acc[ci][g][1] + fb.y + xa.y;
            float u10 = acc[ci][g][2] + fb.x + xb.x;
            float u11 = acc[ci][g][3] + fb.y + xb.y;
            s0 += u00 + u01; ss0 += u00 * u00 + u01 * u01;
            s1 += u10 + u11; ss1 += u10 * u10 + u11 * u11;
        }
    #pragma unroll
    for (int o = 1; o <= 2; o <<= 1) {
        s0  += __shfl_xor_sync(0xffffffffu, s0, o);
        ss0 += __shfl_xor_sync(0xffffffffu, ss0, o);
        s1  += __shfl_xor_sync(0xffffffffu, s1, o);
        ss1 += __shfl_xor_sync(0xffffffffu, ss1, o);
    }
    float* sred = (float*)(smem + F_SRED);
    if ((lane & 3) == 0) {
        sred[(wid * 16 + r0) * 2 + 0]       = s0;
        sred[(wid * 16 + r0) * 2 + 1]       = ss0;
        sred[(wid * 16 + r0 + 8) * 2 + 0]   = s1;
        sred[(wid * 16 + r0 + 8) * 2 + 1]   = ss1;
    }
    __syncthreads();
    float* mure = (float*)(smem + F_MURE);
    if (tid < 16) {
        float s = 0.f, ss = 0.f;
        #pragma unroll
        for (int w = 0; w < 8; ++w) {
            s  += sred[(w * 16 + tid) * 2 + 0];
            ss += sred[(w * 16 + tid) * 2 + 1];
        }
        float mu  = s * (1.f / E_DIM);
        float var = ss * (1.f / E_DIM) - mu * mu;
        mure[tid * 2 + 0] = mu;
        mure[tid * 2 + 1] = rsqrtf(var + 1e-5f);
    }
    __syncthreads();
    float mu0 = mure[r0 * 2],       rs0 = mure[r0 * 2 + 1];
    float mu1 = mure[(r0 + 8) * 2], rs1 = mure[(r0 + 8) * 2 + 1];

    // ---- normalize + write fp32 out ----
    #pragma unroll
    for (int ci = 0; ci < 8; ++ci)
        #pragma unroll
        for (int g = 0; g < 2; ++g) {
            int col = ci * 128 + wid * 16 + g * 8 + 2 * (lane & 3);
            float2 fb = *(const float2*)&flb[col];
            float2 wv = *(const float2*)&n2w[col];
            float2 bv = *(const float2*)&n2b[col];
            float2 xa = __half22float2(*(const __half2*)(smem + F_X1S + r0 * F_X1RB + col * 2));
            float2 xb = __half22float2(*(const __half2*)(smem + F_X1S + (r0 + 8) * F_X1RB + col * 2));
            float2 o0, o1;
            o0.x = (acc[ci][g][0] + fb.x + xa.x - mu0) * rs0 * wv.x + bv.x;
            o0.y = (acc[ci][g][1] + fb.y + xa.y - mu0) * rs0 * wv.y + bv.y;
            o1.x = (acc[ci][g][2] + fb.x + xb.x - mu1) * rs1 * wv.x + bv.x;
            o1.y = (acc[ci][g][3] + fb.y + xb.y - mu1) * rs1 * wv.y + bv.y;
            *(float2*)(out + (size_t)(m0 + r0) * E_DIM + col)     = o0;
            *(float2*)(out + (size_t)(m0 + r0 + 8) * E_DIM + col) = o1;
        }
}

// ---------------- fused prep: z->fp16 | opw->fp16 | flw->fp16 ------------
union HPack { __half h[4]; uint2 u; };
#define ZBLK  (M_TOK * E_DIM / 4 / 256)          // 16384
#define W1BLK (E_DIM * E_DIM / 4 / 256)          // 1024
#define W2BLK (E_DIM * NQ / 4 / 256)             // 64

__global__ __launch_bounds__(256) void prep_kernel(
    const float* __restrict__ x,   const float* __restrict__ aqp,
    __half* __restrict__ zh,
    const float* __restrict__ opw, __half* __restrict__ wh,
    const float* __restrict__ flw, __half* __restrict__ w2h) {
    int bid = blockIdx.x;
    if (bid < ZBLK) {
        __shared__ float sa0[NQ], sc1[NQ];
        if (threadIdx.x < NQ) {
            sa0[threadIdx.x] = aqp[threadIdx.x * 3 + 0];
            sc1[threadIdx.x] = __cosf(aqp[threadIdx.x * 3 + 1]);
        }
        __syncthreads();
        int i = bid * 256 + threadIdx.x;
        int d = (i * 4) & 63;
        float4 v = ((const float4*)x)[i];
        HPack h;
        h.h[0] = __float2half(__cosf(v.x + sa0[d + 0]) * sc1[d + 0]);
        h.h[1] = __float2half(__cosf(v.y + sa0[d + 1]) * sc1[d + 1]);
        h.h[2] = __float2half(__cosf(v.z + sa0[d + 2]) * sc1[d + 2]);
        h.h[3] = __float2half(__cosf(v.w + sa0[d + 3]) * sc1[d + 3]);
        ((uint2*)zh)[i] = h.u;
    } else if (bid < ZBLK + W1BLK) {
        int i = (bid - ZBLK) * 256 + threadIdx.x;
        float4 v = ((const float4*)opw)[i];
        HPack h;
        h.h[0] = __float2half(v.x); h.h[1] = __float2half(v.y);
        h.h[2] = __float2half(v.z); h.h[3] = __float2half(v.w);
        ((uint2*)wh)[i] = h.u;
    } else {
        int i = (bid - ZBLK - W1BLK) * 256 + threadIdx.x;
        float4 v = ((const float4*)flw)[i];
        HPack h;
        h.h[0] = __float2half(v.x); h.h[1] = __float2half(v.y);
        h.h[2] = __float2half(v.z); h.h[3] = __float2half(v.w);
        ((uint2*)w2h)[i] = h.u;
    }
}

// ---------------- LN1: x(fp32) + attn(fp16) -> x1(fp16), q(fp16) ---------
__global__ __launch_bounds__(256) void ln1_kernel(const float* __restrict__ x,
                                                  const __half* __restrict__ attn,
                                                  const float* __restrict__ w,
                                                  const float* __restrict__ b,
                                                  const float* __restrict__ fqp,
                                                  __half* __restrict__ x1,
                                                  __half* __restrict__ qh) {
    int row  = blockIdx.x * 8 + (threadIdx.x >> 5);
    int lane = threadIdx.x & 31;
    const float4* px = (const float4*)(x    + (size_t)row * E_DIM);
    const uint2*  pa = (const uint2*)(attn + (size_t)row * E_DIM);
    float4 v[8];
    float s = 0.f, ss = 0.f;
    #pragma unroll
    for (int j = 0; j < 8; ++j) {
        float4 a = px[lane + j * 32];
        uint2 t = pa[lane + j * 32];
        float2 f0 = __half22float2(*(__half2*)&t.x);
        float2 f1 = __half22float2(*(__half2*)&t.y);
        float4 u = {a.x + f0.x, a.y + f0.y, a.z + f1.x, a.w + f1.y};
        v[j] = u;
        s  += u.x + u.y + u.z + u.w;
        ss += u.x * u.x + u.y * u.y + u.z * u.z + u.w * u.w;
    }
    #pragma unroll
    for (int o = 16; o; o >>= 1) {
        s  += __shfl_xor_sync(0xffffffffu, s, o);
        ss += __shfl_xor_sync(0xffffffffu, ss, o);
    }
    float mu  = s * (1.f / E_DIM);
    float var = ss * (1.f / E_DIM) - mu * mu;
    float rs  = rsqrtf(var + 1e-5f);

    uint2* po = (uint2*)(x1 + (size_t)row * E_DIM);
    #pragma unroll
    for (int j = 0; j < 8; ++j) {
        int c4 = lane + j * 32;
        float4 wv = ((const float4*)w)[c4];
        float4 bv = ((const float4*)b)[c4];
        float4 u  = v[j];
        float4 o;
        o.x = (u.x - mu) * rs * wv.x + bv.x;
        o.y = (u.y - mu) * rs * wv.y + bv.y;
        o.z = (u.z - mu) * rs * wv.z + bv.z;
        o.w = (u.w - mu) * rs * wv.w + bv.w;
        HPack hp;
        hp.h[0] = __float2half(o.x); hp.h[1] = __float2half(o.y);
        hp.h[2] = __float2half(o.z); hp.h[3] = __float2half(o.w);
        po[c4] = hp.u;
        if (j == 0 && lane < 16) {
            int k = lane * 4;
            HPack hq;
            hq.h[0] = __float2half(__cosf(o.x + fqp[(k + 0) * 3]) * __cosf(fqp[(k + 0) * 3 + 1]));
            hq.h[1] = __float2half(__cosf(o.y + fqp[(k + 1) * 3]) * __cosf(fqp[(k + 1) * 3 + 1]));
            hq.h[2] = __float2half(__cosf(o.z + fqp[(k + 2) * 3]) * __cosf(fqp[(k + 2) * 3 + 1]));
            hq.h[3] = __float2half(__cosf(o.w + fqp[(k + 3) * 3]) * __cosf(fqp[(k + 3) * 3 + 1]));
            *(uint2*)(qh + (size_t)row * NQ + k) = hq.u;
        }
    }
}

// ---------------- launcher ----------------
extern "C" void kernel_launch(void* const* d_in, const int* in_sizes, int n_in,
                              void* d_out, int out_size) {
    const float* x   = (const float*)d_in[0];
    const float* aqp = (const float*)d_in[1];
    const float* opw = (const float*)d_in[2];
    const float* opb = (const float*)d_in[3];
    const float* fqp = (const float*)d_in[4];
    const float* flw = (const float*)d_in[5];
    const float* flb = (const float*)d_in[6];
    const float* n1w = (const float*)d_in[7];
    const float* n1b = (const float*)d_in[8];
    const float* n2w = (const float*)d_in[9];
    const float* n2b = (const float*)d_in[10];
    float* out = (float*)d_out;

    __half *attnh, *x1h, *zh, *wh, *w2h, *qh;
    cudaGetSymbolAddress((void**)&attnh, g_attn);
    cudaGetSymbolAddress((void**)&x1h,   g_x1h);
    cudaGetSymbolAddress((void**)&zh,    g_zh);
    cudaGetSymbolAddress((void**)&wh,    g_wh);
    cudaGetSymbolAddress((void**)&w2h,   g_w2h);
    cudaGetSymbolAddress((void**)&qh,    g_qh);

    cudaFuncSetAttribute(mma_gemm, cudaFuncAttributeMaxDynamicSharedMemorySize, SM_TOT);
    cudaFuncSetAttribute(gemm2_ln2, cudaFuncAttributeMaxDynamicSharedMemorySize, F_TOT);

    // 1) fused prep
    prep_kernel<<<ZBLK + W1BLK + W2BLK, 256>>>(x, aqp, zh, opw, wh, flw, w2h);
    // 2) attn = z @ opw^T + opb  (r10-proven GEMM, fp16 out)
    dim3 g1(E_DIM / BN, M_TOK / BM);
    mma_gemm<<<g1, 128, SM_TOT>>>(zh, wh, opb, attnh, E_DIM);
    // 3) x1 = LN1(x + attn) -> fp16; q -> fp16
    ln1_kernel<<<M_TOK / 8, 256>>>(x, attnh, n1w, n1b, fqp, x1h, qh);
    // 4) out = LN2(x1 + q @ flw^T + flb)  (fused, 4-stage ring, fp32 out)
    gemm2_ln2<<<M_TOK / 16, 256, F_TOT>>>(qh, w2h, flb, x1h, n2w, n2b, out);
}

// round 16
// speedup vs baseline: 1.0419x; 1.0419x over previous
#include <cuda_runtime.h>
#include <cuda_fp16.h>
#include <cstdint>

#define M_TOK 16384   // B*S
#define E_DIM 1024
#define NQ    64

// ---------------- scratch (__device__ globals; no allocs) ----------------
__device__ __half g_attn[(size_t)M_TOK * E_DIM];   // fp16 attn
__device__ __half g_zh[(size_t)M_TOK * E_DIM];     // A of GEMM1
__device__ __half g_wh[(size_t)E_DIM * E_DIM];     // B of GEMM1
__device__ __half g_w2h[(size_t)E_DIM * NQ];       // B of GEMM2

// ---------------- PTX helpers (compute_100-safe) -------------------------
__device__ __forceinline__ uint32_t smem_u32(const void* p) {
    uint32_t a;
    asm("{ .reg .u64 t; cvta.to.shared.u64 t, %1; cvt.u32.u64 %0, t; }" : "=r"(a) : "l"(p));
    return a;
}
__device__ __forceinline__ void cp16(uint32_t dst, const void* src) {
    asm volatile("cp.async.cg.shared.global [%0], [%1], 16;" :: "r"(dst), "l"(src));
}
#define CP_COMMIT() asm volatile("cp.async.commit_group;" ::: "memory")
#define CP_WAIT1()  asm volatile("cp.async.wait_group 1;" ::: "memory")
#define CP_WAIT3()  asm volatile("cp.async.wait_group 3;" ::: "memory")
#define CP_WAIT0()  asm volatile("cp.async.wait_group 0;" ::: "memory")

#define LDSM4(r, addr)                                                        \
    asm volatile("ldmatrix.sync.aligned.m8n8.x4.shared.b16 {%0,%1,%2,%3}, [%4];" \
        : "=r"((r)[0]), "=r"((r)[1]), "=r"((r)[2]), "=r"((r)[3]) : "r"(addr))

#define MMA16816(d, a, b0, b1)                                                \
    asm volatile("mma.sync.aligned.m16n8k16.row.col.f32.f16.f16.f32 "         \
        "{%0,%1,%2,%3}, {%4,%5,%6,%7}, {%8,%9}, {%0,%1,%2,%3};"               \
        : "+f"((d)[0]), "+f"((d)[1]), "+f"((d)[2]), "+f"((d)[3])              \
        : "r"((a)[0]), "r"((a)[1]), "r"((a)[2]), "r"((a)[3]),                 \
          "r"(b0), "r"(b1))

// ================= GEMM1: r10-proven fp16 GEMM (fp16 out) ================
#define BM 128
#define BN 128
#define BK 64
#define ROWB 144
#define MAT_B (128 * ROWB)           // 18432
#define STG   (2 * MAT_B)            // 36864
#define SM_BIAS (2 * STG)
#define SM_TOT  (SM_BIAS + BN * 4)

__global__ __launch_bounds__(128, 2) void mma_gemm(
    const __half* __restrict__ Ah, const __half* __restrict__ Bh,
    const float* __restrict__ bias, __half* __restrict__ Cout, int K) {
    extern __shared__ char smem[];
    const uint32_t sbase = smem_u32(smem);
    float* sbias = (float*)(smem + SM_BIAS);
    const int tid = threadIdx.x, wid = tid >> 5, lane = tid & 31;
    const int m0 = blockIdx.y * BM, n0 = blockIdx.x * BN;
    const int m_off = (wid & 1) * 64;
    const int n_off = (wid >> 1) * 64;

    sbias[tid] = bias[n0 + tid];

    const uint32_t aRow = (uint32_t)(m_off + (lane & 15)) * ROWB + (lane >> 4) * 16;
    const uint32_t bRow = (uint32_t)(n_off + ((lane >> 4) << 3) + (lane & 7)) * ROWB
                        + ((lane >> 3) & 1) * 16;

    float acc[4][8][4] = {};

    auto load_stage = [&](int s, int kc0) {
        uint32_t sb = sbase + s * STG;
        #pragma unroll
        for (int i = 0; i < 8; ++i) {
            int c = tid + i * 128;
            int r = c >> 3, ch = c & 7;
            uint32_t d = (uint32_t)r * ROWB + ch * 16;
            cp16(sb + d,         Ah + (size_t)(m0 + r) * K + kc0 + ch * 8);
            cp16(sb + MAT_B + d, Bh + (size_t)(n0 + r) * K + kc0 + ch * 8);
        }
        CP_COMMIT();
    };

    const int C = K / BK;
    load_stage(0, 0);

    for (int ki = 0; ki < C; ++ki) {
        int cur = ki & 1;
        if (ki + 1 < C) { load_stage(cur ^ 1, (ki + 1) * BK); CP_WAIT1(); }
        else           { CP_WAIT0(); }
        __syncthreads();

        uint32_t base = sbase + cur * STG;
        uint32_t aH = base + aRow;
        uint32_t bH = base + MAT_B + bRow;

        #pragma unroll
        for (int ks = 0; ks < 4; ++ks) {
            uint32_t ah[4][4], bh[8][2];
            #pragma unroll
            for (int mi = 0; mi < 4; ++mi)
                LDSM4(ah[mi], aH + ks * 32 + mi * 16 * ROWB);
            #pragma unroll
            for (int p = 0; p < 4; ++p) {
                uint32_t t[4];
                LDSM4(t, bH + ks * 32 + p * 16 * ROWB);
                bh[2 * p][0] = t[0]; bh[2 * p][1] = t[1];
                bh[2 * p + 1][0] = t[2]; bh[2 * p + 1][1] = t[3];
            }
            #pragma unroll
            for (int mi = 0; mi < 4; ++mi)
                #pragma unroll
                for (int ni = 0; ni < 8; ++ni)
                    MMA16816(acc[mi][ni], ah[mi], bh[ni][0], bh[ni][1]);
        }
        __syncthreads();
    }

    #pragma unroll
    for (int mi = 0; mi < 4; ++mi) {
        int m = m0 + m_off + mi * 16 + (lane >> 2);
        #pragma unroll
        for (int ni = 0; ni < 8; ++ni) {
            int nl = n_off + ni * 8 + 2 * (lane & 3);
            float2 bv = *(float2*)&sbias[nl];
            __half* p0 = Cout + (size_t)m * E_DIM + n0 + nl;
            __half* p1 = p0 + 8 * E_DIM;
            *(__half2*)p0 = __floats2half2_rn(acc[mi][ni][0] + bv.x, acc[mi][ni][1] + bv.y);
            *(__half2*)p1 = __floats2half2_rn(acc[mi][ni][2] + bv.x, acc[mi][ni][3] + bv.y);
        }
    }
}

// ================= fused tail: LN1 + q + GEMM2 + LN2 =====================
// CTA: 16 rows x N=1024, 256 threads / 8 warps.
// Phases: stage attn+chunk0/1 -> LN1 (u = x+attn, in-place x1 fp16) -> q ->
//         W2 chunk MMA loop (4-stage ring, WAIT3 trailing-commit) -> LN2.
#define G_RING 0                         // 4 * 18432 = 73728
#define G_CHK  18432
#define G_U    73728                     // 16 rows * 2064 B = 33024
#define G_URB  2064
#define G_Q    106752                    // 16 * 144 = 2304
#define G_PRM  109056                    // sa0[64], sc1[64] = 512
#define G_SRED 109568                    // 8*16*2 floats = 1024
#define G_MURE 110592                    // 16*2 floats = 128
#define G_TOT  110720                    // -> 2 CTAs/SM

__global__ __launch_bounds__(256, 2) void fused_tail(
    const float* __restrict__ x, const __half* __restrict__ attn,
    const float* __restrict__ n1w, const float* __restrict__ n1b,
    const float* __restrict__ fqp, const __half* __restrict__ w2h,
    const float* __restrict__ flb,
    const float* __restrict__ n2w, const float* __restrict__ n2b,
    float* __restrict__ out) {
    extern __shared__ char smem[];
    const uint32_t sbase = smem_u32(smem);
    const int tid = threadIdx.x, wid = tid >> 5, lane = tid & 31;
    const int m0 = blockIdx.x * 16;
    const int r0 = lane >> 2;
    float* sred = (float*)(smem + G_SRED);
    float* mure = (float*)(smem + G_MURE);
    float* sa0  = (float*)(smem + G_PRM);
    float* sc1  = sa0 + NQ;

    auto load_chunk = [&](int ci) {      // W2 chunk ci -> stage ci&3
        uint32_t sb = sbase + (ci & 3) * G_CHK;
        #pragma unroll
        for (int i = 0; i < 4; ++i) {
            int u = tid + i * 256;
            int r = u >> 3, c = u & 7;
            cp16(sb + (uint32_t)r * 144 + c * 16,
                 w2h + (size_t)(ci * 128 + r) * NQ + c * 8);
        }
    };

    // g0: attn tile -> U (fp16) + chunk0 ; params via plain LDG/STS
    #pragma unroll
    for (int i = 0; i < 8; ++i) {
        int u = tid + i * 256;
        int r = u >> 7, c = u & 127;
        cp16(sbase + G_U + (uint32_t)r * G_URB + c * 16,
             attn + (size_t)(m0 + r) * E_DIM + c * 8);
    }
    load_chunk(0);
    if (tid < NQ) {
        sa0[tid] = fqp[tid * 3 + 0];
        sc1[tid] = __cosf(fqp[tid * 3 + 1]);
    }
    CP_COMMIT();                         // g0
    load_chunk(1); CP_COMMIT();          // g1

    CP_WAIT1();
    __syncthreads();                     // attn + chunk0 + params visible

    // ---- Phase B: u = x + attn (in place, fp16), LN1 stats ----
    float s0 = 0.f, ss0 = 0.f, s1 = 0.f, ss1 = 0.f;
    #pragma unroll
    for (int ci = 0; ci < 8; ++ci)
        #pragma unroll
        for (int g = 0; g < 2; ++g) {
            int col = ci * 128 + wid * 16 + g * 8 + 2 * (lane & 3);
            float2 xa = *(const float2*)&x[(size_t)(m0 + r0) * E_DIM + col];
            float2 xb = *(const float2*)&x[(size_t)(m0 + r0 + 8) * E_DIM + col];
            __half2* pua = (__half2*)(smem + G_U + r0 * G_URB + col * 2);
            __half2* pub = (__half2*)(smem + G_U + (r0 + 8) * G_URB + col * 2);
            float2 aa = __half22float2(*pua);
            float2 ab = __half22float2(*pub);
            float u00 = xa.x + aa.x, u01 = xa.y + aa.y;
            float u10 = xb.x + ab.x, u11 = xb.y + ab.y;
            *pua = __floats2half2_rn(u00, u01);
            *pub = __floats2half2_rn(u10, u11);
            s0 += u00 + u01; ss0 += u00 * u00 + u01 * u01;
            s1 += u10 + u11; ss1 += u10 * u10 + u11 * u11;
        }
    #pragma unroll
    for (int o = 1; o <= 2; o <<= 1) {
        s0  += __shfl_xor_sync(0xffffffffu, s0, o);
        ss0 += __shfl_xor_sync(0xffffffffu, ss0, o);
        s1  += __shfl_xor_sync(0xffffffffu, s1, o);
        ss1 += __shfl_xor_sync(0xffffffffu, ss1, o);
    }
    if ((lane & 3) == 0) {
        sred[(wid * 16 + r0) * 2 + 0]     = s0;
        sred[(wid * 16 + r0) * 2 + 1]     = ss0;
        sred[(wid * 16 + r0 + 8) * 2 + 0] = s1;
        sred[(wid * 16 + r0 + 8) * 2 + 1] = ss1;
    }
    __syncthreads();
    if (tid < 16) {
        float s = 0.f, ss = 0.f;
        #pragma unroll
        for (int w = 0; w < 8; ++w) {
            s  += sred[(w * 16 + tid) * 2 + 0];
            ss += sred[(w * 16 + tid) * 2 + 1];
        }
        float mu  = s * (1.f / E_DIM);
        float var = ss * (1.f / E_DIM) - mu * mu;
        mure[tid * 2 + 0] = mu;
        mure[tid * 2 + 1] = rsqrtf(var + 1e-5f);
    }
    __syncthreads();

    // ---- Phase C: x1 = LN1 in place (fp16); q (cols 0..63) -> G_Q ----
    {
        float mu0 = mure[r0 * 2],       rs0 = mure[r0 * 2 + 1];
        float mu1 = mure[(r0 + 8) * 2], rs1 = mure[(r0 + 8) * 2 + 1];
        #pragma unroll
        for (int ci = 0; ci < 8; ++ci)
            #pragma unroll
            for (int g = 0; g < 2; ++g) {
                int col = ci * 128 + wid * 16 + g * 8 + 2 * (lane & 3);
                float2 wv = *(const float2*)&n1w[col];
                float2 bv = *(const float2*)&n1b[col];
                __half2* pua = (__half2*)(smem + G_U + r0 * G_URB + col * 2);
                __half2* pub = (__half2*)(smem + G_U + (r0 + 8) * G_URB + col * 2);
                float2 ua = __half22float2(*pua);
                float2 ub = __half22float2(*pub);
                float o00 = (ua.x - mu0) * rs0 * wv.x + bv.x;
                float o01 = (ua.y - mu0) * rs0 * wv.y + bv.y;
                float o10 = (ub.x - mu1) * rs1 * wv.x + bv.x;
                float o11 = (ub.y - mu1) * rs1 * wv.y + bv.y;
                *pua = __floats2half2_rn(o00, o01);
                *pub = __floats2half2_rn(o10, o11);
                if (ci == 0 && wid < 4) {
                    float q00 = __cosf(o00 + sa0[col])     * sc1[col];
                    float q01 = __cosf(o01 + sa0[col + 1]) * sc1[col + 1];
                    float q10 = __cosf(o10 + sa0[col])     * sc1[col];
                    float q11 = __cosf(o11 + sa0[col + 1]) * sc1[col + 1];
                    *(__half2*)(smem + G_Q + r0 * 144 + col * 2)       = __floats2half2_rn(q00, q01);
                    *(__half2*)(smem + G_Q + (r0 + 8) * 144 + col * 2) = __floats2half2_rn(q10, q11);
                }
            }
    }
    __syncthreads();                     // x1 + q published

    load_chunk(2); CP_COMMIT();          // g2
    load_chunk(3); CP_COMMIT();          // g3

    // A fragments from q (q visible after sync above)
    uint32_t aF[4][4];
    #pragma unroll
    for (int ks = 0; ks < 4; ++ks)
        LDSM4(aF[ks], sbase + G_Q + (uint32_t)(lane & 15) * 144
                           + (lane >> 4) * 16 + ks * 32);

    float acc[8][2][4] = {};
    const uint32_t bRow = (uint32_t)((wid * 16) + ((lane >> 4) << 3) + (lane & 7)) * 144
                        + ((lane >> 3) & 1) * 16;

    for (int ci = 0; ci < 8; ++ci) {
        CP_WAIT3();               // committed g0..g_{3+ci}; g_ci (chunk ci) done
        __syncthreads();
        uint32_t Bb = sbase + (ci & 3) * G_CHK + bRow;
        #pragma unroll
        for (int ks = 0; ks < 4; ++ks) {
            uint32_t t[4];
            LDSM4(t, Bb + ks * 32);
            MMA16816(acc[ci][0], aF[ks], t[0], t[1]);
            MMA16816(acc[ci][1], aF[ks], t[2], t[3]);
        }
        __syncthreads();          // all warps done with stage ci&3
        if (ci + 4 < 8) load_chunk(ci + 4);
        CP_COMMIT();
    }
    CP_WAIT0();

    // ---- LN2: stats over u(x1 fp16) + acc + flb ----
    s0 = 0.f; ss0 = 0.f; s1 = 0.f; ss1 = 0.f;
    #pragma unroll
    for (int ci = 0; ci < 8; ++ci)
        #pragma unroll
        for (int g = 0; g < 2; ++g) {
            int col = ci * 128 + wid * 16 + g * 8 + 2 * (lane & 3);
            float2 fb = *(const float2*)&flb[col];
            float2 xa = __half22float2(*(const __half2*)(smem + G_U + r0 * G_URB + col * 2));
            float2 xb = __half22float2(*(const __half2*)(smem + G_U + (r0 + 8) * G_URB + col * 2));
            float u00 = acc[ci][g][0] + fb.x + xa.x;
            float u01 = acc[ci][g][1] + fb.y + xa.y;
            float u10 = acc[ci][g][2] + fb.x + xb.x;
            float u11 = acc[ci][g][3] + fb.y + xb.y;
            s0 += u00 + u01; ss0 += u00 * u00 + u01 * u01;
            s1 += u10 + u11; ss1 += u10 * u10 + u11 * u11;
        }
    #pragma unroll
    for (int o = 1; o <= 2; o <<= 1) {
        s0  += __shfl_xor_sync(0xffffffffu, s0, o);
        ss0 += __shfl_xor_sync(0xffffffffu, ss0, o);
        s1  += __shfl_xor_sync(0xffffffffu, s1, o);
        ss1 += __shfl_xor_sync(0xffffffffu, ss1, o);
    }
    __syncthreads();              // mure/sred reuse safe
    if ((lane & 3) == 0) {
        sred[(wid * 16 + r0) * 2 + 0]     = s0;
        sred[(wid * 16 + r0) * 2 + 1]     = ss0;
        sred[(wid * 16 + r0 + 8) * 2 + 0] = s1;
        sred[(wid * 16 + r0 + 8) * 2 + 1] = ss1;
    }
    __syncthreads();
    if (tid < 16) {
        float s = 0.f, ss = 0.f;
        #pragma unroll
        for (int w = 0; w < 8; ++w) {
            s  += sred[(w * 16 + tid) * 2 + 0];
            ss += sred[(w * 16 + tid) * 2 + 1];
        }
        float mu  = s * (1.f / E_DIM);
        float var = ss * (1.f / E_DIM) - mu * mu;
        mure[tid * 2 + 0] = mu;
        mure[tid * 2 + 1] = rsqrtf(var + 1e-5f);
    }
    __syncthreads();
    float mu0 = mure[r0 * 2],       rs0 = mure[r0 * 2 + 1];
    float mu1 = mure[(r0 + 8) * 2], rs1 = mure[(r0 + 8) * 2 + 1];

    #pragma unroll
    for (int ci = 0; ci < 8; ++ci)
        #pragma unroll
        for (int g = 0; g < 2; ++g) {
            int col = ci * 128 + wid * 16 + g * 8 + 2 * (lane & 3);
            float2 fb = *(const float2*)&flb[col];
            float2 wv = *(const float2*)&n2w[col];
            float2 bv = *(const float2*)&n2b[col];
            float2 xa = __half22float2(*(const __half2*)(smem + G_U + r0 * G_URB + col * 2));
            float2 xb = __half22float2(*(const __half2*)(smem + G_U + (r0 + 8) * G_URB + col * 2));
            float2 o0, o1;
            o0.x = (acc[ci][g][0] + fb.x + xa.x - mu0) * rs0 * wv.x + bv.x;
            o0.y = (acc[ci][g][1] + fb.y + xa.y - mu0) * rs0 * wv.y + bv.y;
            o1.x = (acc[ci][g][2] + fb.x + xb.x - mu1) * rs1 * wv.x + bv.x;
            o1.y = (acc[ci][g][3] + fb.y + xb.y - mu1) * rs1 * wv.y + bv.y;
            *(float2*)(out + (size_t)(m0 + r0) * E_DIM + col)     = o0;
            *(float2*)(out + (size_t)(m0 + r0 + 8) * E_DIM + col) = o1;
        }
}

// ---------------- fused prep: z->fp16 | opw->fp16 | flw->fp16 ------------
union HPack { __half h[4]; uint2 u; };
#define ZBLK  (M_TOK * E_DIM / 4 / 256)          // 16384
#define W1BLK (E_DIM * E_DIM / 4 / 256)          // 1024
#define W2BLK (E_DIM * NQ / 4 / 256)             // 64

__global__ __launch_bounds__(256) void prep_kernel(
    const float* __restrict__ x,   const float* __restrict__ aqp,
    __half* __restrict__ zh,
    const float* __restrict__ opw, __half* __restrict__ wh,
    const float* __restrict__ flw, __half* __restrict__ w2h) {
    int bid = blockIdx.x;
    if (bid < ZBLK) {
        __shared__ float sa0[NQ], sc1[NQ];
        if (threadIdx.x < NQ) {
            sa0[threadIdx.x] = aqp[threadIdx.x * 3 + 0];
            sc1[threadIdx.x] = __cosf(aqp[threadIdx.x * 3 + 1]);
        }
        __syncthreads();
        int i = bid * 256 + threadIdx.x;
        int d = (i * 4) & 63;
        float4 v = ((const float4*)x)[i];
        HPack h;
        h.h[0] = __float2half(__cosf(v.x + sa0[d + 0]) * sc1[d + 0]);
        h.h[1] = __float2half(__cosf(v.y + sa0[d + 1]) * sc1[d + 1]);
        h.h[2] = __float2half(__cosf(v.z + sa0[d + 2]) * sc1[d + 2]);
        h.h[3] = __float2half(__cosf(v.w + sa0[d + 3]) * sc1[d + 3]);
        ((uint2*)zh)[i] = h.u;
    } else if (bid < ZBLK + W1BLK) {
        int i = (bid - ZBLK) * 256 + threadIdx.x;
        float4 v = ((const float4*)opw)[i];
        HPack h;
        h.h[0] = __float2half(v.x); h.h[1] = __float2half(v.y);
        h.h[2] = __float2half(v.z); h.h[3] = __float2half(v.w);
        ((uint2*)wh)[i] = h.u;
    } else {
        int i = (bid - ZBLK - W1BLK) * 256 + threadIdx.x;
        float4 v = ((const float4*)flw)[i];
        HPack h;
        h.h[0] = __float2half(v.x); h.h[1] = __float2half(v.y);
        h.h[2] = __float2half(v.z); h.h[3] = __float2half(v.w);
        ((uint2*)w2h)[i] = h.u;
    }
}

// ---------------- launcher ----------------
extern "C" void kernel_launch(void* const* d_in, const int* in_sizes, int n_in,
                              void* d_out, int out_size) {
    const float* x   = (const float*)d_in[0];
    const float* aqp = (const float*)d_in[1];
    const float* opw = (const float*)d_in[2];
    const float* opb = (const float*)d_in[3];
    const float* fqp = (const float*)d_in[4];
    const float* flw = (const float*)d_in[5];
    const float* flb = (const float*)d_in[6];
    const float* n1w = (const float*)d_in[7];
    const float* n1b = (const float*)d_in[8];
    const float* n2w = (const float*)d_in[9];
    const float* n2b = (const float*)d_in[10];
    float* out = (float*)d_out;

    __half *attnh, *zh, *wh, *w2h;
    cudaGetSymbolAddress((void**)&attnh, g_attn);
    cudaGetSymbolAddress((void**)&zh,    g_zh);
    cudaGetSymbolAddress((void**)&wh,    g_wh);
    cudaGetSymbolAddress((void**)&w2h,   g_w2h);

    cudaFuncSetAttribute(mma_gemm,   cudaFuncAttributeMaxDynamicSharedMemorySize, SM_TOT);
    cudaFuncSetAttribute(fused_tail, cudaFuncAttributeMaxDynamicSharedMemorySize, G_TOT);

    // 1) fused prep
    prep_kernel<<<ZBLK + W1BLK + W2BLK, 256>>>(x, aqp, zh, opw, wh, flw, w2h);
    // 2) attn = z @ opw^T + opb  (r10-proven GEMM, fp16 out)
    dim3 g1(E_DIM / BN, M_TOK / BM);
    mma_gemm<<<g1, 128, SM_TOT>>>(zh, wh, opb, attnh, E_DIM);
    // 3) out = LN2(LN1(x+attn) + q@flw^T + flb)  (fully fused tail)
    fused_tail<<<M_TOK / 16, 256, G_TOT>>>(x, attnh, n1w, n1b, fqp, w2h,
                                           flb, n2w, n2b, out);
}